// round 13
// baseline (speedup 1.0000x reference)
#include <cuda_runtime.h>
#include <cuda_bf16.h>
#include <stdint.h>

// exact x % n for 0 <= x < 2^31 (fixups cover float-induced q error of +-2)
__device__ __forceinline__ int fast_mod(int x, int n, float invnf)
{
    int q = (int)((float)x * invnf);
    int r = x - q * n;
    if (r < 0)  r += n;
    if (r < 0)  r += n;
    if (r >= n) r -= n;
    if (r >= n) r -= n;
    return r;
}

// ===========================================================================
// Phase 1 (sub2), fast path: deg2==64, D==128. One 256-thread block per type
// column; warp w sums 8 of the 64 edge rows (float4, 32 lanes = 512B row),
// smem reduce across 8 warps, warp 0 adds base + type row and writes.
// ===========================================================================
__global__ void __launch_bounds__(256)
sub2_f4_kernel(const float4* __restrict__ emb4,
               const int*    __restrict__ s2r,
               const int*    __restrict__ ls,
               const int*    __restrict__ rc,
               float4*       __restrict__ out4,
               int n_ent)
{
    __shared__ int    rows[64];
    __shared__ float4 part[7][32];

    const int c    = blockIdx.x;
    const int t    = threadIdx.x;
    const int lane = t & 31;
    const int w    = t >> 5;          // 0..7

    if (t < 64) rows[t] = ls[__ldg(s2r + c * 64 + t)];
    __syncthreads();

    float4 acc = make_float4(0.f, 0.f, 0.f, 0.f);
    #pragma unroll
    for (int e = 0; e < 8; ++e) {
        const int r = rows[w * 8 + e];
        float4 v = __ldg(emb4 + (size_t)r * 32 + lane);
        acc.x += v.x; acc.y += v.y; acc.z += v.z; acc.w += v.w;
    }

    if (w > 0) part[w - 1][lane] = acc;
    __syncthreads();

    if (w == 0) {
        #pragma unroll
        for (int i = 0; i < 7; ++i) {
            float4 p = part[i][lane];
            acc.x += p.x; acc.y += p.y; acc.z += p.z; acc.w += p.w;
        }
        const float base = (float)n_ent - 64.0f;
        const int   tr   = __ldg(rc + c);
        float4 iv = __ldg(emb4 + (size_t)tr * 32 + lane);
        float4 r;
        r.x = iv.x + acc.x + base;
        r.y = iv.y + acc.y + base;
        r.z = iv.z + acc.z + base;
        r.w = iv.w + acc.w + base;
        out4[(size_t)tr * 32 + lane] = r;
    }
}

// Generic sub2 fallback (any deg2 / D).
__global__ void sub2_gen_kernel(const float* __restrict__ emb,
                                const int*   __restrict__ s2r,
                                const int*   __restrict__ ls,
                                const int*   __restrict__ rc,
                                float*       __restrict__ out,
                                int deg2, int n_ent, int D)
{
    extern __shared__ int rows[];
    const int c = blockIdx.x;
    for (int i = threadIdx.x; i < deg2; i += blockDim.x)
        rows[i] = ls[s2r[(size_t)c * deg2 + i]];
    __syncthreads();

    const int d = threadIdx.x;
    if (d >= D) return;
    float acc = (float)n_ent - (float)deg2;
    #pragma unroll 8
    for (int e = 0; e < deg2; ++e)
        acc += emb[(size_t)rows[e] * D + d];
    const int t = rc[c];
    out[(size_t)t * D + d] = emb[(size_t)t * D + d] + acc;
}

// ===========================================================================
// Phase 2 (sub3): one warp per entity, fully self-verifying speculation.
// Hypothesis: s3r[4*ent+j] == (m*ent+j) % n_typ with m = s3r[4],
//             rs[ent] == ent, lc[w] == n_ent + w for the 4 used windows.
// All checks are warp-uniform broadcast loads verified in parallel with the
// streaming entity-row read; the 4 updated type rows are then gathered
// straight from `out` at ALU-computed addresses (no index chain, no prep
// kernel, no device state). Any mismatch -> exact in-warp gather fallback.
// ===========================================================================
__global__ void __launch_bounds__(256)
sub3_spec_kernel(const float4* __restrict__ emb4,
                 const int*    __restrict__ s3r,
                 const int4*   __restrict__ s3r4,
                 const int*    __restrict__ lc,
                 const int*    __restrict__ rs,
                 float4*       out4,
                 int n_typ, int n_ent, float invnf)
{
    const int ent  = blockIdx.x * 8 + (threadIdx.x >> 5);
    const int lane = threadIdx.x & 31;
    if (ent >= n_ent) return;

    // Speculative streaming read (assumes rs[ent]==ent); issued first.
    float4 iv = __ldcs(emb4 + (size_t)ent * 32 + lane);

    // Broadcast verification data (all hot after first touch).
    const int4 e4  = __ldg(s3r4 + ent);
    const int  rsv = __ldg(rs + ent);
    const int  m   = __ldg(s3r + 4);       // candidate multiplier

    const float base = (float)n_typ - 4.0f;
    const float inv  = 0.2f;               // 1/(1+deg3)

    bool spec = ((unsigned)m < (unsigned)n_typ);
    int w0 = 0, w1 = 0, w2 = 0, w3 = 0;
    if (spec) {
        w0 = fast_mod(m * ent, n_typ, invnf);
        w1 = w0 + 1; if (w1 >= n_typ) w1 -= n_typ;
        w2 = w1 + 1; if (w2 >= n_typ) w2 -= n_typ;
        w3 = w2 + 1; if (w3 >= n_typ) w3 -= n_typ;
        const int l0 = __ldg(lc + w0);
        const int l1 = __ldg(lc + w1);
        const int l2 = __ldg(lc + w2);
        const int l3 = __ldg(lc + w3);
        spec = (e4.x == w0) & (e4.y == w1) & (e4.z == w2) & (e4.w == w3) &
               (rsv == ent) &
               (l0 == n_ent + w0) & (l1 == n_ent + w1) &
               (l2 == n_ent + w2) & (l3 == n_ent + w3);
    }

    if (spec) {
        // 4 L2-hot type rows at ALU-computed addresses.
        float4 v0 = __ldg(out4 + (size_t)(n_ent + w0) * 32 + lane);
        float4 v1 = __ldg(out4 + (size_t)(n_ent + w1) * 32 + lane);
        float4 v2 = __ldg(out4 + (size_t)(n_ent + w2) * 32 + lane);
        float4 v3 = __ldg(out4 + (size_t)(n_ent + w3) * 32 + lane);
        float4 acc;
        acc.x = base + v0.x + v1.x + v2.x + v3.x;
        acc.y = base + v0.y + v1.y + v2.y + v3.y;
        acc.z = base + v0.z + v1.z + v2.z + v3.z;
        acc.w = base + v0.w + v1.w + v2.w + v3.w;
        float4 r;
        r.x = iv.x * (1.0f - acc.x * inv);
        r.y = iv.y * (1.0f - acc.y * inv);
        r.z = iv.z * (1.0f - acc.z * inv);
        r.w = iv.w * (1.0f - acc.w * inv);
        __stcs(out4 + (size_t)ent * 32 + lane, r);
    } else {
        // Exact gather path (arbitrary indices).
        const int tr = rsv;
        float4 ive = __ldcs(emb4 + (size_t)tr * 32 + lane);
        const int t0 = __ldg(lc + e4.x);
        const int t1 = __ldg(lc + e4.y);
        const int t2 = __ldg(lc + e4.z);
        const int t3 = __ldg(lc + e4.w);
        float4 v0 = __ldg(out4 + (size_t)t0 * 32 + lane);
        float4 v1 = __ldg(out4 + (size_t)t1 * 32 + lane);
        float4 v2 = __ldg(out4 + (size_t)t2 * 32 + lane);
        float4 v3 = __ldg(out4 + (size_t)t3 * 32 + lane);
        float4 acc;
        acc.x = base + v0.x + v1.x + v2.x + v3.x;
        acc.y = base + v0.y + v1.y + v2.y + v3.y;
        acc.z = base + v0.z + v1.z + v2.z + v3.z;
        acc.w = base + v0.w + v1.w + v2.w + v3.w;
        float4 r;
        r.x = ive.x * (1.0f - acc.x * inv);
        r.y = ive.y * (1.0f - acc.y * inv);
        r.z = ive.z * (1.0f - acc.z * inv);
        r.w = ive.w * (1.0f - acc.w * inv);
        __stcs(out4 + (size_t)tr * 32 + lane, r);
    }
}

// Generic sub3 fallback (any deg3 / D).
__global__ void sub3_gen_kernel(const float* __restrict__ emb,
                                const int*   __restrict__ s3r,
                                const int*   __restrict__ lc,
                                const int*   __restrict__ rs,
                                float*       out,
                                int deg3, int n_typ, int n_ent, int D)
{
    const int tpe  = D >> 2;
    const int epb  = blockDim.x / tpe;
    const int ent  = blockIdx.x * epb + threadIdx.x / tpe;
    const int lane = threadIdx.x % tpe;
    if (ent >= n_ent) return;

    const float base = (float)n_typ - (float)deg3;
    float4 acc = make_float4(base, base, base, base);
    const int* er = s3r + (size_t)ent * deg3;
    const float4* out4 = (const float4*)out;
    for (int e = 0; e < deg3; ++e) {
        const int t = lc[er[e]];
        float4 v = out4[(size_t)t * tpe + lane];
        acc.x += v.x; acc.y += v.y; acc.z += v.z; acc.w += v.w;
    }
    const float inv = 1.0f / (1.0f + (float)deg3);
    const int t = rs[ent];
    float4 iv = ((const float4*)emb)[(size_t)t * tpe + lane];
    float4 r;
    r.x = iv.x * (1.0f - acc.x * inv);
    r.y = iv.y * (1.0f - acc.y * inv);
    r.z = iv.z * (1.0f - acc.z * inv);
    r.w = iv.w * (1.0f - acc.w * inv);
    ((float4*)out)[(size_t)t * tpe + lane] = r;
}

// ===========================================================================
// Inputs (metadata order):
//  0 all_node_embedding f32 [(n_ent+n_typ)*D]
//  1 sub2_row i32   2 sub2_col i32   3 sub3_row i32   4 sub3_col i32
//  5 left_specific i32 [n_ent]   6 right_common i32 [n_typ]
//  7 left_common  i32 [n_typ]    8 right_specific i32 [n_ent]
// Type rows U entity rows cover the whole output -> no copy kernel.
// ===========================================================================
extern "C" void kernel_launch(void* const* d_in, const int* in_sizes, int n_in,
                              void* d_out, int out_size)
{
    const float* emb = (const float*)d_in[0];
    const int*   s2r = (const int*)d_in[1];
    const int*   s3r = (const int*)d_in[3];
    const int*   ls  = (const int*)d_in[5];
    const int*   rc  = (const int*)d_in[6];
    const int*   lc  = (const int*)d_in[7];
    const int*   rs  = (const int*)d_in[8];
    float* out = (float*)d_out;

    const int n_ent = in_sizes[5];
    const int n_typ = in_sizes[7];
    const int n3    = in_sizes[3];
    const int D     = in_sizes[0] / (n_ent + n_typ);   // 128
    const int deg2  = in_sizes[1] / n_typ;             // 64
    const int deg3  = n3 / n_ent;                      // 4

    // ---- Phase 1: type rows ----
    if (deg2 == 64 && D == 128) {
        sub2_f4_kernel<<<n_typ, 256>>>(
            (const float4*)emb, s2r, ls, rc, (float4*)out, n_ent);
    } else {
        sub2_gen_kernel<<<n_typ, (D + 31) & ~31, deg2 * (int)sizeof(int)>>>(
            emb, s2r, ls, rc, out, deg2, n_ent, D);
    }

    // ---- Phase 2: entity rows ----
    const bool fastP = (deg3 == 4) && (D == 128) && (n_typ >= 4) && (n3 > 4) &&
                       ((long long)n_typ * (long long)n_ent + 4 < (1LL << 31));
    if (fastP) {
        const float invnf = 1.0f / (float)n_typ;
        const int grid = (n_ent + 7) / 8;
        sub3_spec_kernel<<<grid, 256>>>(
            (const float4*)emb, s3r, (const int4*)s3r, lc, rs, (float4*)out,
            n_typ, n_ent, invnf);
    } else {
        const int tpe = D >> 2;
        const int block = 256;
        const int epb = block / tpe;
        const int grid = (n_ent + epb - 1) / epb;
        sub3_gen_kernel<<<grid, block>>>(
            emb, s3r, lc, rs, out, deg3, n_typ, n_ent, D);
    }
}

// round 14
// speedup vs baseline: 1.1496x; 1.1496x over previous
#include <cuda_runtime.h>
#include <cuda_bf16.h>
#include <stdint.h>

// ===========================================================================
// Speculation state.
//   g_bad: zero-initialized at module load; latched to 1 by sub2's verifier
//   whenever the structural hypothesis fails. Never cleared — with fixed
//   inputs every replay recomputes the same value (0 stays 0 on good data;
//   bad data re-latches 1 every replay), so behavior is deterministic.
//   Hypothesis: s3r[4*ent+j] == (m*ent+j) % n_typ with m = s3r[4],
//               rs[ent] == ent,  lc[t] == n_ent + t.
//   g_P4[w] = T[w] + T[(w+1)%M] + T[(w+2)%M] + T[(w+3)%M] (updated type rows)
// ===========================================================================
#define TYP_MAX_ROWS 8192
__device__ int    g_bad;                       // BSS zero-init
__device__ float4 g_P4[TYP_MAX_ROWS * 32];

// exact x % n for 0 <= x < 2^31 (fixups cover float-induced q error)
__device__ __forceinline__ int fast_mod(int x, int n, float invnf)
{
    int q = (int)((float)x * invnf);
    int r = x - q * n;
    if (r < 0)  r += n;
    if (r < 0)  r += n;
    if (r >= n) r -= n;
    if (r >= n) r -= n;
    return r;
}

// Grid-stride structural verifier; latches g_bad on any mismatch.
__device__ __forceinline__ void verify_structure(
    const int* __restrict__ s3r, const int4* __restrict__ s3r4,
    const int* __restrict__ lc,  const int* __restrict__ rs,
    int n_ent, int n_typ, float invnf)
{
    const int m = __ldg(s3r + 4);
    if ((unsigned)m >= (unsigned)n_typ) {
        if (blockIdx.x == 0 && threadIdx.x == 0) g_bad = 1;
        return;
    }
    const int stride = gridDim.x * blockDim.x;
    bool bad = false;
    for (int ent = blockIdx.x * blockDim.x + threadIdx.x;
         ent < n_ent; ent += stride) {
        const int4 e = __ldg(s3r4 + ent);
        const int w0 = fast_mod(m * ent, n_typ, invnf);
        int w1 = w0 + 1; if (w1 >= n_typ) w1 -= n_typ;
        int w2 = w1 + 1; if (w2 >= n_typ) w2 -= n_typ;
        int w3 = w2 + 1; if (w3 >= n_typ) w3 -= n_typ;
        bad |= (e.x != w0) | (e.y != w1) | (e.z != w2) | (e.w != w3);
        bad |= (__ldg(rs + ent) != ent);
        if (ent < n_typ) bad |= (__ldg(lc + ent) != n_ent + ent);
    }
    if (bad) g_bad = 1;
}

// ===========================================================================
// Phase 1 (sub2), fast path: deg2==64, D==128. One 128-thr block per type
// column; warp w sums 16 edge rows (float4), smem reduce, warp 0 writes.
// Optionally runs the structural verifier (independent loads hidden under
// this kernel's latency-bound profile).
// ===========================================================================
__global__ void sub2_f4_kernel(const float4* __restrict__ emb4,
                               const int*    __restrict__ s2r,
                               const int*    __restrict__ ls,
                               const int*    __restrict__ rc,
                               float4*       __restrict__ out4,
                               int n_ent, int n_typ, int doVerify,
                               const int* __restrict__ s3r,
                               const int4* __restrict__ s3r4,
                               const int* __restrict__ lc,
                               const int* __restrict__ rs, float invnf)
{
    __shared__ int    rows[64];
    __shared__ float4 part[3][32];

    const int c    = blockIdx.x;
    const int t    = threadIdx.x;
    const int lane = t & 31;
    const int w    = t >> 5;

    if (t < 64) rows[t] = ls[__ldg(s2r + c * 64 + t)];
    __syncthreads();

    float4 acc = make_float4(0.f, 0.f, 0.f, 0.f);
    #pragma unroll
    for (int e = 0; e < 16; ++e) {
        const int r = rows[e * 4 + w];
        float4 v = __ldg(emb4 + (size_t)r * 32 + lane);
        acc.x += v.x; acc.y += v.y; acc.z += v.z; acc.w += v.w;
    }

    if (w > 0) part[w - 1][lane] = acc;
    __syncthreads();

    if (w == 0) {
        #pragma unroll
        for (int i = 0; i < 3; ++i) {
            float4 p = part[i][lane];
            acc.x += p.x; acc.y += p.y; acc.z += p.z; acc.w += p.w;
        }
        const float base = (float)n_ent - 64.0f;
        const int   tr   = __ldg(rc + c);
        float4 iv = __ldg(emb4 + (size_t)tr * 32 + lane);
        float4 r;
        r.x = iv.x + acc.x + base;
        r.y = iv.y + acc.y + base;
        r.z = iv.z + acc.z + base;
        r.w = iv.w + acc.w + base;
        out4[(size_t)tr * 32 + lane] = r;
    }

    if (doVerify)
        verify_structure(s3r, s3r4, lc, rs, n_ent, n_typ, invnf);
}

// Generic sub2 fallback (any deg2 / D); also runs the verifier when needed.
__global__ void sub2_gen_kernel(const float* __restrict__ emb,
                                const int*   __restrict__ s2r,
                                const int*   __restrict__ ls,
                                const int*   __restrict__ rc,
                                float*       __restrict__ out,
                                int deg2, int n_ent, int D,
                                int n_typ, int doVerify,
                                const int* __restrict__ s3r,
                                const int4* __restrict__ s3r4,
                                const int* __restrict__ lc,
                                const int* __restrict__ rs, float invnf)
{
    extern __shared__ int rows[];
    const int c = blockIdx.x;
    for (int i = threadIdx.x; i < deg2; i += blockDim.x)
        rows[i] = ls[s2r[(size_t)c * deg2 + i]];
    __syncthreads();

    const int d = threadIdx.x;
    if (d < D) {
        float acc = (float)n_ent - (float)deg2;
        #pragma unroll 8
        for (int e = 0; e < deg2; ++e)
            acc += emb[(size_t)rows[e] * D + d];
        const int t = rc[c];
        out[(size_t)t * D + d] = emb[(size_t)t * D + d] + acc;
    }

    if (doVerify)
        verify_structure(s3r, s3r4, lc, rs, n_ent, n_typ, invnf);
}

// ===========================================================================
// Prep (winsum only): one warp per window, P[w] = circular 4-row sum of the
// updated type rows. 125 blocks for n_typ=1000; type rows are L2-hot.
// ===========================================================================
__global__ void prep_kernel(const float4* __restrict__ out4,
                            int n_ent, int n_typ)
{
    const int win  = blockIdx.x * 8 + (threadIdx.x >> 5);
    const int lane = threadIdx.x & 31;
    if (win >= n_typ) return;

    int w1 = win + 1; if (w1 >= n_typ) w1 -= n_typ;
    int w2 = win + 2; if (w2 >= n_typ) w2 -= n_typ;
    int w3 = win + 3; if (w3 >= n_typ) w3 -= n_typ;

    float4 a = out4[(size_t)(n_ent + win) * 32 + lane];
    float4 b = out4[(size_t)(n_ent + w1)  * 32 + lane];
    float4 c = out4[(size_t)(n_ent + w2)  * 32 + lane];
    float4 d = out4[(size_t)(n_ent + w3)  * 32 + lane];
    float4 s;
    s.x = a.x + b.x + c.x + d.x;
    s.y = a.y + b.y + c.y + d.y;
    s.z = a.z + b.z + c.z + d.z;
    s.w = a.w + b.w + c.w + d.w;
    g_P4[(size_t)win * 32 + lane] = s;
}

// ===========================================================================
// Phase 2 (sub3): one warp per entity (R9-proven shape). Verified path:
// broadcast g_bad + m, fast_mod, ONE P gather, streaming entity read/write.
// Zero per-warp verification. g_bad -> exact gather path.
// ===========================================================================
__global__ void __launch_bounds__(256)
sub3_spec_kernel(const float4* __restrict__ emb4,
                 const int*    __restrict__ s3r,
                 const int4*   __restrict__ s3r4,
                 const int*    __restrict__ lc,
                 const int*    __restrict__ rs,
                 float4*       out4,
                 int n_typ, int n_ent, float invnf)
{
    const int ent  = blockIdx.x * 8 + (threadIdx.x >> 5);
    const int lane = threadIdx.x & 31;
    if (ent >= n_ent) return;

    const float base = (float)n_typ - 4.0f;
    const float inv  = 0.2f;   // 1/(1+deg3)
    const int bad = g_bad;                 // broadcast, L2-hot
    const int m   = __ldg(s3r + 4);        // broadcast, L2-hot

    if (!bad) {
        const int w0 = fast_mod(m * ent, n_typ, invnf);
        float4 iv = __ldcs(emb4 + (size_t)ent * 32 + lane);  // rs[ent]==ent
        float4 s  = g_P4[(size_t)w0 * 32 + lane];
        float4 r;
        r.x = iv.x * (1.0f - (base + s.x) * inv);
        r.y = iv.y * (1.0f - (base + s.y) * inv);
        r.z = iv.z * (1.0f - (base + s.z) * inv);
        r.w = iv.w * (1.0f - (base + s.w) * inv);
        __stcs(out4 + (size_t)ent * 32 + lane, r);
    } else {
        const int4 e4 = __ldg(s3r4 + ent);
        const int  tr = __ldg(rs + ent);
        float4 iv = __ldcs(emb4 + (size_t)tr * 32 + lane);
        const int t0 = __ldg(lc + e4.x);
        const int t1 = __ldg(lc + e4.y);
        const int t2 = __ldg(lc + e4.z);
        const int t3 = __ldg(lc + e4.w);
        float4 v0 = __ldg(out4 + (size_t)t0 * 32 + lane);
        float4 v1 = __ldg(out4 + (size_t)t1 * 32 + lane);
        float4 v2 = __ldg(out4 + (size_t)t2 * 32 + lane);
        float4 v3 = __ldg(out4 + (size_t)t3 * 32 + lane);
        float4 acc;
        acc.x = base + v0.x + v1.x + v2.x + v3.x;
        acc.y = base + v0.y + v1.y + v2.y + v3.y;
        acc.z = base + v0.z + v1.z + v2.z + v3.z;
        acc.w = base + v0.w + v1.w + v2.w + v3.w;
        float4 r;
        r.x = iv.x * (1.0f - acc.x * inv);
        r.y = iv.y * (1.0f - acc.y * inv);
        r.z = iv.z * (1.0f - acc.z * inv);
        r.w = iv.w * (1.0f - acc.w * inv);
        __stcs(out4 + (size_t)tr * 32 + lane, r);
    }
}

// Generic sub3 fallback (any deg3 / D).
__global__ void sub3_gen_kernel(const float* __restrict__ emb,
                                const int*   __restrict__ s3r,
                                const int*   __restrict__ lc,
                                const int*   __restrict__ rs,
                                float*       out,
                                int deg3, int n_typ, int n_ent, int D)
{
    const int tpe  = D >> 2;
    const int epb  = blockDim.x / tpe;
    const int ent  = blockIdx.x * epb + threadIdx.x / tpe;
    const int lane = threadIdx.x % tpe;
    if (ent >= n_ent) return;

    const float base = (float)n_typ - (float)deg3;
    float4 acc = make_float4(base, base, base, base);
    const int* er = s3r + (size_t)ent * deg3;
    const float4* out4 = (const float4*)out;
    for (int e = 0; e < deg3; ++e) {
        const int t = lc[er[e]];
        float4 v = out4[(size_t)t * tpe + lane];
        acc.x += v.x; acc.y += v.y; acc.z += v.z; acc.w += v.w;
    }
    const float inv = 1.0f / (1.0f + (float)deg3);
    const int t = rs[ent];
    float4 iv = ((const float4*)emb)[(size_t)t * tpe + lane];
    float4 r;
    r.x = iv.x * (1.0f - acc.x * inv);
    r.y = iv.y * (1.0f - acc.y * inv);
    r.z = iv.z * (1.0f - acc.z * inv);
    r.w = iv.w * (1.0f - acc.w * inv);
    ((float4*)out)[(size_t)t * tpe + lane] = r;
}

// ===========================================================================
// Inputs (metadata order):
//  0 all_node_embedding f32 [(n_ent+n_typ)*D]
//  1 sub2_row i32   2 sub2_col i32   3 sub3_row i32   4 sub3_col i32
//  5 left_specific i32 [n_ent]   6 right_common i32 [n_typ]
//  7 left_common  i32 [n_typ]    8 right_specific i32 [n_ent]
// Type rows U entity rows cover the whole output -> no copy kernel.
// ===========================================================================
extern "C" void kernel_launch(void* const* d_in, const int* in_sizes, int n_in,
                              void* d_out, int out_size)
{
    const float* emb = (const float*)d_in[0];
    const int*   s2r = (const int*)d_in[1];
    const int*   s3r = (const int*)d_in[3];
    const int*   ls  = (const int*)d_in[5];
    const int*   rc  = (const int*)d_in[6];
    const int*   lc  = (const int*)d_in[7];
    const int*   rs  = (const int*)d_in[8];
    float* out = (float*)d_out;

    const int n_ent = in_sizes[5];
    const int n_typ = in_sizes[7];
    const int n3    = in_sizes[3];
    const int D     = in_sizes[0] / (n_ent + n_typ);   // 128
    const int deg2  = in_sizes[1] / n_typ;             // 64
    const int deg3  = n3 / n_ent;                      // 4

    const bool fastP = (deg3 == 4) && (D == 128) && (n_typ >= 4) && (n3 > 4) &&
                       (n_typ <= TYP_MAX_ROWS) &&
                       ((long long)n_typ * (long long)n_ent + 4 < (1LL << 31));
    const float invnf = 1.0f / (float)n_typ;
    const int doVerify = fastP ? 1 : 0;

    // ---- Phase 1: type rows (+ structural verification, hidden) ----
    if (deg2 == 64 && D == 128) {
        sub2_f4_kernel<<<n_typ, 128>>>(
            (const float4*)emb, s2r, ls, rc, (float4*)out, n_ent, n_typ,
            doVerify, s3r, (const int4*)s3r, lc, rs, invnf);
    } else {
        sub2_gen_kernel<<<n_typ, (D + 31) & ~31, deg2 * (int)sizeof(int)>>>(
            emb, s2r, ls, rc, out, deg2, n_ent, D, n_typ,
            doVerify, s3r, (const int4*)s3r, lc, rs, invnf);
    }

    // ---- Phase 2: entity rows ----
    if (fastP) {
        prep_kernel<<<(n_typ + 7) / 8, 256>>>(
            (const float4*)out, n_ent, n_typ);
        const int grid = (n_ent + 7) / 8;
        sub3_spec_kernel<<<grid, 256>>>(
            (const float4*)emb, s3r, (const int4*)s3r, lc, rs, (float4*)out,
            n_typ, n_ent, invnf);
    } else {
        const int tpe = D >> 2;
        const int block = 256;
        const int epb = block / tpe;
        const int grid = (n_ent + epb - 1) / epb;
        sub3_gen_kernel<<<grid, block>>>(
            emb, s3r, lc, rs, out, deg3, n_typ, n_ent, D);
    }
}